// round 4
// baseline (speedup 1.0000x reference)
#include <cuda_runtime.h>
#include <cstdint>

// Row-wise top-k(=6) thresholded renormalization.
//   delta = (6th largest of row) + 1e-7
//   w     = max(v - delta, 0) ;  out = w / (sum(w) + 1e-7)
//
// One block per row, 256 threads, one float4 per thread (1024 cols).
// R3: candidate-pruned selection. Threshold t = 6th largest of the 8 warp
// maxes (8 distinct row elements => t <= true kth). All elements >= t are
// compacted to shared; warp 0 extracts the exact 6th largest of that
// candidate multiset (generic loop — exact for ANY input, fast when few
// candidates, which is the typical case).

#define COLS 1024
#define TOPK 6
#define EPSV 1e-7f

__device__ __forceinline__ unsigned redux_max_u32(unsigned v) {
    unsigned r;
    asm volatile("redux.sync.max.u32 %0, %1, %2;"
                 : "=r"(r) : "r"(v), "r"(0xffffffffu));
    return r;
}

// monotone bijection: float ordering -> u32 ordering (exact, invertible)
__device__ __forceinline__ unsigned fkey(float f) {
    unsigned b = __float_as_uint(f);
    return b ^ ((unsigned)((int)b >> 31) | 0x80000000u);
}
__device__ __forceinline__ float funkey(unsigned k) {
    unsigned b = (k & 0x80000000u) ? (k ^ 0x80000000u) : ~k;
    return __uint_as_float(b);
}

__global__ __launch_bounds__(256, 8)
void topk_renorm_kernel(const float* __restrict__ in,
                        float* __restrict__ out) {
    const int row  = blockIdx.x;
    const int tid  = threadIdx.x;
    const int lane = tid & 31;
    const int warp = tid >> 5;

    __shared__ unsigned sh_wmax[8];
    __shared__ unsigned sh_cand[1024];   // worst-case capacity: whole row
    __shared__ int      sh_n;
    __shared__ float    sh_t;
    __shared__ float    sh_sum[8];
    __shared__ float    sh_delta;
    __shared__ float    sh_rinv;

    if (tid == 0) sh_n = 0;

    const float4* rp = reinterpret_cast<const float4*>(in + (size_t)row * COLS);
    float4 v = __ldcs(rp + tid);

    // ---- stage A: per-warp max (float max tree, one key, one redux) ----
    float lmf = fmaxf(fmaxf(v.x, v.y), fmaxf(v.z, v.w));
    unsigned wm = redux_max_u32(fkey(lmf));
    if (lane == 0) sh_wmax[warp] = wm;
    __syncthreads();

    // ---- stage B: warp 0: t = 6th largest of the 8 warp maxes ----
    if (warp == 0) {
        unsigned a = (lane < 8) ? sh_wmax[lane] : 0u;
        unsigned kth = 0u;
#pragma unroll
        for (int r = 0; r < TOPK; ++r) {
            unsigned m = redux_max_u32(a);
            kth = m;
            unsigned msk = __ballot_sync(0xffffffffu, a == m);
            if (lane == (__ffs((int)msk) - 1)) a = 0u;
        }
        if (lane == 0) sh_t = funkey(kth);
    }
    __syncthreads();

    // ---- stage C: compact candidates (v >= t); contains the true top-6 ----
    const float t = sh_t;
    if (v.x >= t) sh_cand[atomicAdd(&sh_n, 1)] = fkey(v.x);
    if (v.y >= t) sh_cand[atomicAdd(&sh_n, 1)] = fkey(v.y);
    if (v.z >= t) sh_cand[atomicAdd(&sh_n, 1)] = fkey(v.z);
    if (v.w >= t) sh_cand[atomicAdd(&sh_n, 1)] = fkey(v.w);
    __syncthreads();

    // ---- stage D: warp 0: exact 6th largest of the n candidates ----
    if (warp == 0) {
        const int n = sh_n;          // n >= TOPK by construction
        unsigned kth = 0u;
#pragma unroll 1
        for (int r = 0; r < TOPK; ++r) {
            unsigned lm = 0u;
            for (int i = lane; i < n; i += 32) lm = max(lm, sh_cand[i]);
            unsigned m = redux_max_u32(lm);
            kth = m;
            // remove exactly one instance of m (exact multiset semantics)
            int idx = -1;
            for (int i = lane; i < n; i += 32)
                if (sh_cand[i] == m) { idx = i; break; }
            unsigned msk = __ballot_sync(0xffffffffu, idx >= 0);
            if (lane == (__ffs((int)msk) - 1)) sh_cand[idx] = 0u;
            __syncwarp();
        }
        if (lane == 0) sh_delta = funkey(kth) + EPSV;
    }
    __syncthreads();

    // ---- epilogue: clamp, sum, normalize, store ----
    const float delta = sh_delta;
    float w0 = fmaxf(v.x - delta, 0.0f);
    float w1 = fmaxf(v.y - delta, 0.0f);
    float w2 = fmaxf(v.z - delta, 0.0f);
    float w3 = fmaxf(v.w - delta, 0.0f);

    float s = (w0 + w1) + (w2 + w3);
#pragma unroll
    for (int o = 16; o > 0; o >>= 1)
        s += __shfl_xor_sync(0xffffffffu, s, o);
    if (lane == 0) sh_sum[warp] = s;
    __syncthreads();

    if (tid == 0) {
        float tt = EPSV;
#pragma unroll
        for (int i = 0; i < 8; ++i) tt += sh_sum[i];
        sh_rinv = 1.0f / tt;
    }
    __syncthreads();

    const float rinv = sh_rinv;
    float4 o4;
    o4.x = w0 * rinv;
    o4.y = w1 * rinv;
    o4.z = w2 * rinv;
    o4.w = w3 * rinv;
    __stcs(reinterpret_cast<float4*>(out + (size_t)row * COLS) + tid, o4);
}

extern "C" void kernel_launch(void* const* d_in, const int* in_sizes, int n_in,
                              void* d_out, int out_size) {
    const float* in = (const float*)d_in[0];
    float* out = (float*)d_out;
    const int rows = in_sizes[0] / COLS;   // 65536 for the reference shape
    topk_renorm_kernel<<<rows, 256>>>(in, out);
}

// round 5
// speedup vs baseline: 2.3803x; 2.3803x over previous
#include <cuda_runtime.h>
#include <cstdint>

// Row-wise top-k(=6) thresholded renormalization.
//   delta = (6th largest of row) + 1e-7
//   w     = max(v - delta, 0) ;  out = w / (sum(w) + 1e-7)
//
// R5: one WARP per row (32 threads x 32 elems), zero block barriers.
//   t   = 6th largest of the 32 per-thread maxes  (provably <= true 6th)
//   cand= all elements >= t  (contains the top-6 multiset; buffer holds a
//         full row so this is exact for ANY input)
//   v6  = 6th largest of cand (iterative extraction, exact dup handling)

#define COLS   1024
#define TOPK   6
#define EPSV   1e-7f
#define WPB    8            // warps (=rows) per block

__device__ __forceinline__ unsigned redux_max_u32(unsigned v) {
    unsigned r;
    asm volatile("redux.sync.max.u32 %0, %1, %2;"
                 : "=r"(r) : "r"(v), "r"(0xffffffffu));
    return r;
}
// monotone bijection: float ordering -> u32 ordering (exact, invertible)
__device__ __forceinline__ unsigned fkey(float f) {
    unsigned b = __float_as_uint(f);
    return b ^ ((unsigned)((int)b >> 31) | 0x80000000u);
}
__device__ __forceinline__ float funkey(unsigned k) {
    unsigned b = (k & 0x80000000u) ? (k ^ 0x80000000u) : ~k;
    return __uint_as_float(b);
}
__device__ __forceinline__ float4 fmax4(float4 a, float4 b) {
    return make_float4(fmaxf(a.x,b.x), fmaxf(a.y,b.y),
                       fmaxf(a.z,b.z), fmaxf(a.w,b.w));
}

__global__ __launch_bounds__(32 * WPB)
void topk_renorm_kernel(const float* __restrict__ in,
                        float* __restrict__ out, int rows) {
    const int lane = threadIdx.x & 31;
    const int warp = threadIdx.x >> 5;
    const int row  = blockIdx.x * WPB + warp;
    if (row >= rows) return;

    __shared__ unsigned sh_cand[WPB][COLS];   // full-row capacity per warp
    __shared__ int      sh_cnt[WPB];

    // ---- load: 32 elems/thread as 8 float4 (MLP=8) ----
    const float4* rp = reinterpret_cast<const float4*>(in + (size_t)row * COLS);
    float4 v[8];
#pragma unroll
    for (int i = 0; i < 8; ++i) v[i] = __ldcs(rp + lane + 32 * i);

    // ---- per-thread max (31 FMNMX tree) ----
    float4 m01 = fmax4(v[0], v[1]), m23 = fmax4(v[2], v[3]);
    float4 m45 = fmax4(v[4], v[5]), m67 = fmax4(v[6], v[7]);
    float4 mm  = fmax4(fmax4(m01, m23), fmax4(m45, m67));
    float lmax = fmaxf(fmaxf(mm.x, mm.y), fmaxf(mm.z, mm.w));

    // ---- t = 6th largest of the 32 thread-maxes (warp-local rounds) ----
    unsigned a = fkey(lmax);
    unsigned kth = 0u;
#pragma unroll
    for (int r = 0; r < TOPK; ++r) {
        unsigned m = redux_max_u32(a);
        kth = m;
        unsigned msk = __ballot_sync(0xffffffffu, a == m);
        if (lane == (__ffs((int)msk) - 1)) a = 0u;
    }
    const float t = funkey(kth);     // identical on all lanes

    // ---- compact candidates (v >= t) into this warp's buffer ----
    if (lane == 0) sh_cnt[warp] = 0;
    __syncwarp();
    if (lmax >= t) {                 // most threads skip the whole scan
#pragma unroll
        for (int i = 0; i < 8; ++i) {
            if (v[i].x >= t) sh_cand[warp][atomicAdd(&sh_cnt[warp],1)] = fkey(v[i].x);
            if (v[i].y >= t) sh_cand[warp][atomicAdd(&sh_cnt[warp],1)] = fkey(v[i].y);
            if (v[i].z >= t) sh_cand[warp][atomicAdd(&sh_cnt[warp],1)] = fkey(v[i].z);
            if (v[i].w >= t) sh_cand[warp][atomicAdd(&sh_cnt[warp],1)] = fkey(v[i].w);
        }
    }
    __syncwarp();

    // ---- exact 6th largest of the n candidates (n >= 6 by construction) ----
    const int n = sh_cnt[warp];
    unsigned kk = 0u;
#pragma unroll 1
    for (int r = 0; r < TOPK; ++r) {
        unsigned lm = 0u;
        for (int i = lane; i < n; i += 32) lm = max(lm, sh_cand[warp][i]);
        unsigned m = redux_max_u32(lm);
        kk = m;
        int idx = -1;                          // remove exactly one instance
        for (int i = lane; i < n; i += 32)
            if (sh_cand[warp][i] == m) { idx = i; break; }
        unsigned msk = __ballot_sync(0xffffffffu, idx >= 0);
        if (lane == (__ffs((int)msk) - 1)) sh_cand[warp][idx] = 0u;
        __syncwarp();
    }
    const float delta = funkey(kk) + EPSV;     // identical on all lanes

    // ---- epilogue: clamp, warp sum, normalize, store ----
    float4 w[8];
    float4 acc = make_float4(0.f, 0.f, 0.f, 0.f);
#pragma unroll
    for (int i = 0; i < 8; ++i) {
        w[i].x = fmaxf(v[i].x - delta, 0.0f);
        w[i].y = fmaxf(v[i].y - delta, 0.0f);
        w[i].z = fmaxf(v[i].z - delta, 0.0f);
        w[i].w = fmaxf(v[i].w - delta, 0.0f);
        acc.x += w[i].x; acc.y += w[i].y; acc.z += w[i].z; acc.w += w[i].w;
    }
    float s = (acc.x + acc.y) + (acc.z + acc.w);
#pragma unroll
    for (int o = 16; o > 0; o >>= 1)
        s += __shfl_xor_sync(0xffffffffu, s, o);
    const float rinv = 1.0f / (s + EPSV);      // identical on all lanes

    float4* op = reinterpret_cast<float4*>(out + (size_t)row * COLS);
#pragma unroll
    for (int i = 0; i < 8; ++i) {
        float4 o4;
        o4.x = w[i].x * rinv; o4.y = w[i].y * rinv;
        o4.z = w[i].z * rinv; o4.w = w[i].w * rinv;
        __stcs(op + lane + 32 * i, o4);
    }
}

extern "C" void kernel_launch(void* const* d_in, const int* in_sizes, int n_in,
                              void* d_out, int out_size) {
    const float* in = (const float*)d_in[0];
    float* out = (float*)d_out;
    const int rows = in_sizes[0] / COLS;           // 65536 for reference shape
    const int grid = (rows + WPB - 1) / WPB;
    topk_renorm_kernel<<<grid, 32 * WPB>>>(in, out, rows);
}